// round 4
// baseline (speedup 1.0000x reference)
#include <cuda_runtime.h>

#define BATCH   4096
#define FEAT    40960
#define ACCUM   512
#define H1      32
#define MAXIDX  128

// Scratch (device globals — no allocations allowed)
__device__ float g_ftT[(size_t)FEAT * ACCUM];   // transposed ft weights [FEAT][ACCUM]
__device__ int   g_stm_mode;                    // 0 = byte bool, 1 = int32, 2 = float32

// ---------------------------------------------------------------------------
// K0: detect stm dtype (reads only first 4096 bytes — safe under all layouts).
// ---------------------------------------------------------------------------
__global__ void k0_prep(const unsigned char* __restrict__ stm) {
    __shared__ int bad_int, bad_f32;
    if (threadIdx.x == 0) { bad_int = 0; bad_f32 = 0; }
    __syncthreads();
    for (int g = threadIdx.x; g < 1024; g += blockDim.x) {
        unsigned char b0 = stm[4*g+0], b1 = stm[4*g+1];
        unsigned char b2 = stm[4*g+2], b3 = stm[4*g+3];
        if (!((b1 | b2 | b3) == 0 && b0 <= 1)) atomicOr(&bad_int, 1);
        bool zero = (b0 | b1 | b2 | b3) == 0;
        bool one  = (b0 == 0 && b1 == 0 && b2 == 0x80 && b3 == 0x3F);
        if (!(zero || one)) atomicOr(&bad_f32, 1);
    }
    __syncthreads();
    if (threadIdx.x == 0)
        g_stm_mode = (!bad_int) ? 1 : ((!bad_f32) ? 2 : 0);
}

// ---------------------------------------------------------------------------
// K1: transpose ft_w [ACCUM, FEAT] -> g_ftT [FEAT, ACCUM] (tiled 32x32).
// ---------------------------------------------------------------------------
__global__ void transpose_kernel(const float* __restrict__ ftw) {
    __shared__ float tile[32][33];
    int fx = blockIdx.x * 32;
    int oy = blockIdx.y * 32;
    int tx = threadIdx.x, ty = threadIdx.y;   // block (32, 8)
    #pragma unroll
    for (int j = 0; j < 32; j += 8)
        tile[ty + j][tx] = ftw[(size_t)(oy + ty + j) * FEAT + (fx + tx)];
    __syncthreads();
    #pragma unroll
    for (int j = 0; j < 32; j += 8)
        g_ftT[(size_t)(fx + ty + j) * ACCUM + (oy + tx)] = tile[tx][ty + j];
}

// ---------------------------------------------------------------------------
// Emit indices of nonzero elements in a uint4 (values are 0.0f/1.0f bit-exact)
// ---------------------------------------------------------------------------
__device__ __forceinline__ void emit(uint4 v, int base, int* cnt, int* idx) {
    if (v.x | v.y | v.z | v.w) {
        if (v.x) { int p = atomicAdd(cnt, 1); if (p < MAXIDX) idx[p] = base + 0; }
        if (v.y) { int p = atomicAdd(cnt, 1); if (p < MAXIDX) idx[p] = base + 1; }
        if (v.z) { int p = atomicAdd(cnt, 1); if (p < MAXIDX) idx[p] = base + 2; }
        if (v.w) { int p = atomicAdd(cnt, 1); if (p < MAXIDX) idx[p] = base + 3; }
    }
}

// ---------------------------------------------------------------------------
// K2: NNUE forward. One block per batch row, 512 threads.
// Scan: 4 independent uint4 loads per iteration, fully unrolled, cheap
// bitwise zero fast-path -> deep load window (high MLP) to saturate HBM.
// ---------------------------------------------------------------------------
__global__ __launch_bounds__(512, 2) void nnue_kernel(
    const float* __restrict__ wf, const float* __restrict__ bf,
    const unsigned char* __restrict__ stm_raw,
    const float* __restrict__ ft_b,
    const float* __restrict__ l1_w, const float* __restrict__ l1_b,
    const float* __restrict__ l2_w, const float* __restrict__ l2_b,
    const float* __restrict__ out_w, const float* __restrict__ out_b,
    float* __restrict__ out)
{
    const int row = blockIdx.x;
    const int t   = threadIdx.x;

    __shared__ int   idxw[MAXIDX], idxb[MAXIDX];
    __shared__ int   nw, nb;
    __shared__ float x[2 * ACCUM];
    __shared__ float v1[H1];

    if (t == 0) { nw = 0; nb = 0; }
    __syncthreads();

    // ---- Phase A: scan (4 independent 16B loads / iter, unrolled x10) ----
    const uint4* wrow = (const uint4*)(wf + (size_t)row * FEAT);
    const uint4* brow = (const uint4*)(bf + (size_t)row * FEAT);
    #pragma unroll
    for (int i = 0; i < FEAT / 4 / 1024; i++) {   // 10 iterations
        int vi0 = t + (2*i)   * 512;
        int vi1 = t + (2*i+1) * 512;
        uint4 v0 = wrow[vi0];
        uint4 v1r = wrow[vi1];
        uint4 u0 = brow[vi0];
        uint4 u1 = brow[vi1];
        emit(v0,  4*vi0, &nw, idxw);
        emit(v1r, 4*vi1, &nw, idxw);
        emit(u0,  4*vi0, &nb, idxb);
        emit(u1,  4*vi1, &nb, idxb);
    }
    __syncthreads();

    const int cw = min(nw, MAXIDX), cb = min(nb, MAXIDX);

    // ---- Phase B: accumulate with 8-deep load window ----
    float accw;
    {
        float a0=0.f,a1=0.f,a2=0.f,a3=0.f,a4=0.f,a5=0.f,a6=0.f,a7=0.f;
        int k = 0;
        for (; k + 8 <= cw; k += 8) {
            a0 += g_ftT[(size_t)idxw[k+0] * ACCUM + t];
            a1 += g_ftT[(size_t)idxw[k+1] * ACCUM + t];
            a2 += g_ftT[(size_t)idxw[k+2] * ACCUM + t];
            a3 += g_ftT[(size_t)idxw[k+3] * ACCUM + t];
            a4 += g_ftT[(size_t)idxw[k+4] * ACCUM + t];
            a5 += g_ftT[(size_t)idxw[k+5] * ACCUM + t];
            a6 += g_ftT[(size_t)idxw[k+6] * ACCUM + t];
            a7 += g_ftT[(size_t)idxw[k+7] * ACCUM + t];
        }
        for (; k < cw; k++) a0 += g_ftT[(size_t)idxw[k] * ACCUM + t];
        accw = ft_b[t] + ((a0+a1)+(a2+a3)) + ((a4+a5)+(a6+a7));
    }
    float accb;
    {
        float a0=0.f,a1=0.f,a2=0.f,a3=0.f,a4=0.f,a5=0.f,a6=0.f,a7=0.f;
        int k = 0;
        for (; k + 8 <= cb; k += 8) {
            a0 += g_ftT[(size_t)idxb[k+0] * ACCUM + t];
            a1 += g_ftT[(size_t)idxb[k+1] * ACCUM + t];
            a2 += g_ftT[(size_t)idxb[k+2] * ACCUM + t];
            a3 += g_ftT[(size_t)idxb[k+3] * ACCUM + t];
            a4 += g_ftT[(size_t)idxb[k+4] * ACCUM + t];
            a5 += g_ftT[(size_t)idxb[k+5] * ACCUM + t];
            a6 += g_ftT[(size_t)idxb[k+6] * ACCUM + t];
            a7 += g_ftT[(size_t)idxb[k+7] * ACCUM + t];
        }
        for (; k < cb; k++) a0 += g_ftT[(size_t)idxb[k] * ACCUM + t];
        accb = ft_b[t] + ((a0+a1)+(a2+a3)) + ((a4+a5)+(a6+a7));
    }

    // screlu
    accw = fminf(fmaxf(accw, 0.f), 1.f); accw *= accw;
    accb = fminf(fmaxf(accb, 0.f), 1.f); accb *= accb;

    // stm select
    bool s;
    {
        int mode = g_stm_mode;
        if (mode == 1)      s = ((const int*)stm_raw)[row] != 0;
        else if (mode == 2) s = ((const float*)stm_raw)[row] != 0.f;
        else                s = stm_raw[row] != 0;
    }
    x[t]         = s ? accb : accw;
    x[ACCUM + t] = s ? accw : accb;
    __syncthreads();

    // ---- Phase C: L1 (32 outputs x 1024 dot), 16 warps x 2 outputs ----
    const int warp = t >> 5, lane = t & 31;
    #pragma unroll
    for (int oo = 0; oo < 2; oo++) {
        int o = warp * 2 + oo;
        const float* w1 = l1_w + (size_t)o * (2 * ACCUM);
        float sum = 0.f;
        #pragma unroll
        for (int j = lane; j < 2 * ACCUM; j += 32)
            sum += x[j] * __ldg(&w1[j]);
        #pragma unroll
        for (int off = 16; off > 0; off >>= 1)
            sum += __shfl_down_sync(0xffffffffu, sum, off);
        if (lane == 0) {
            sum += l1_b[o];
            sum = fminf(fmaxf(sum, 0.f), 1.f);
            v1[o] = sum * sum;
        }
    }
    __syncthreads();

    // ---- L2 layer + output head (warp 0) ----
    if (warp == 0) {
        float sum = l2_b[lane];
        #pragma unroll
        for (int j = 0; j < H1; j++)
            sum += v1[j] * __ldg(&l2_w[lane * H1 + j]);
        sum = fminf(fmaxf(sum, 0.f), 1.f);
        float vv = sum * sum * __ldg(&out_w[lane]);
        #pragma unroll
        for (int off = 16; off > 0; off >>= 1)
            vv += __shfl_down_sync(0xffffffffu, vv, off);
        if (lane == 0) out[row] = vv + out_b[0];
    }
}

// ---------------------------------------------------------------------------
extern "C" void kernel_launch(void* const* d_in, const int* in_sizes, int n_in,
                              void* d_out, int out_size) {
    const float*         wf    = (const float*)d_in[0];
    const float*         bf    = (const float*)d_in[1];
    const unsigned char* stm   = (const unsigned char*)d_in[2];
    const float*         ft_w  = (const float*)d_in[3];
    const float*         ft_b  = (const float*)d_in[4];
    const float*         l1_w  = (const float*)d_in[5];
    const float*         l1_b  = (const float*)d_in[6];
    const float*         l2_w  = (const float*)d_in[7];
    const float*         l2_b  = (const float*)d_in[8];
    const float*         out_w = (const float*)d_in[9];
    const float*         out_b = (const float*)d_in[10];
    float*               out   = (float*)d_out;

    k0_prep<<<1, 256>>>(stm);

    dim3 tgrid(FEAT / 32, ACCUM / 32);
    dim3 tblock(32, 8);
    transpose_kernel<<<tgrid, tblock>>>(ft_w);

    nnue_kernel<<<BATCH, 512>>>(wf, bf, stm, ft_b, l1_w, l1_b,
                                l2_w, l2_b, out_w, out_b, out);
}